// round 15
// baseline (speedup 1.0000x reference)
#include <cuda_runtime.h>
#include <cuda_fp16.h>
#include <cstdint>
#include <cstddef>

#define BN   16
#define HH   64
#define WW   64
#define CIN  128
#define CO   256
#define NPOS (HH*WW)

// ---------------- scratch ----------------
__device__ uint4  g_wF[9*2*4*4*4*32];               // fragment-ordered fp16 weights
__device__ __half g_x[(size_t)BN*NPOS*CO];          // relu(conv), fp16, 33.5MB
__device__ float g_p0[BN*128*CO];
__device__ float g_p2[BN*512*CO];
__device__ float g_p3[BN*512*CO];
__device__ float g_v1[BN*CO];
__device__ float g_w [BN*CO];
__device__ float g_v3[BN*CO];

// ---------------- helpers ----------------
__device__ __forceinline__ uint32_t smem_u32(const void* p) {
    uint32_t a;
    asm("{ .reg .u64 t; cvta.to.shared.u64 t, %1; cvt.u32.u64 %0, t; }" : "=r"(a) : "l"(p));
    return a;
}
__device__ __forceinline__ void ldm4(uint32_t* r, uint32_t a) {
    asm volatile("ldmatrix.sync.aligned.m8n8.x4.shared.b16 {%0,%1,%2,%3}, [%4];"
                 : "=r"(r[0]), "=r"(r[1]), "=r"(r[2]), "=r"(r[3]) : "r"(a));
}
__device__ __forceinline__ void mma16816(float* c, const uint32_t* a,
                                         uint32_t b0, uint32_t b1) {
    asm volatile(
        "mma.sync.aligned.m16n8k16.row.col.f32.f16.f16.f32 "
        "{%0,%1,%2,%3}, {%4,%5,%6,%7}, {%8,%9}, {%0,%1,%2,%3};"
        : "+f"(c[0]), "+f"(c[1]), "+f"(c[2]), "+f"(c[3])
        : "r"(a[0]), "r"(a[1]), "r"(a[2]), "r"(a[3]), "r"(b0), "r"(b1));
}

// ---------------- prep: fragment-ordered fp16 weights ----------------
__global__ void __launch_bounds__(256)
split_w_kernel(const float* __restrict__ wk)
{
    int t = blockIdx.x*blockDim.x + threadIdx.x;
    if (t >= 36864) return;
    int lane = t & 31;
    int g = t >> 5;
    int ks = g & 3, ng = (g >> 2) & 3, wnIdx = (g >> 4) & 3;
    int cih = (g >> 6) & 1, tap = g >> 7;
    __half h[8];
    #pragma unroll
    for (int j = 0; j < 8; j++) {
        int m = j >> 1, jj = j & 1;
        int n = wnIdx*64 + ng*16 + (m & 1)*8 + (lane >> 2);
        int k = tap*128 + cih*64 + ks*16 + (m >> 1)*8 + (lane & 3)*2 + jj;
        h[j] = __float2half_rn(wk[k*256 + n]);
    }
    g_wF[t] = *(uint4*)h;
}

// ---------------- tensor-core conv ----------------
// CTA: 32m (half image row) x 256n, 128 threads, 4 warps (1m x 4n),
// warp tile 32m x 64n. 4 CTAs/SM (16 warps/SM, 4/SMSP).
#define HALO_B    26112            // 3*34*256
#define CS_OFF    HALO_B
#define BIAS_OFF  (CS_OFF + 1024)
#define SMEM_CONV (BIAS_OFF + 1024)

__global__ void __launch_bounds__(128, 4)
conv_mma_kernel(const float* __restrict__ in, const float* __restrict__ bias)
{
    extern __shared__ char sm[];
    const uint32_t smb = smem_u32(sm);
    const int tid = threadIdx.x;
    const int bx = blockIdx.x;        // 0..127: half-row index
    const int b  = blockIdx.y;
    const int h  = bx >> 1;
    const int w0 = (bx & 1) * 32;

    float* sbias = (float*)(sm + BIAS_OFF);
    sbias[tid]       = bias[tid];
    sbias[tid + 128] = bias[tid + 128];

    const int wid = tid >> 5, lane = tid & 31;
    const int wn = wid * 64;            // n warp 0..3
    const int lmat = lane >> 3, lrow = lane & 7;
    const int fr_row = (lmat & 1)*8 + lrow;
    const int fr_kb  = (lmat >> 1)*16;      // bit 4

    float acc[2][8][4];
    #pragma unroll
    for (int mt = 0; mt < 2; mt++)
        #pragma unroll
        for (int nt = 0; nt < 8; nt++)
            #pragma unroll
            for (int j = 0; j < 4; j++) acc[mt][nt][j] = 0.f;

    // ---- A halo: 3 rows x 34 cols x 16 slots, fp32 -> fp16, swizzled ----
    for (int i = tid; i < 1632; i += 128) {
        int pix  = i >> 4;
        int slot = i & 15;
        int tr = pix / 34, tcc = pix - tr*34;
        int hh = h + tr - 1, w = w0 + tcc - 1;
        bool ok = ((unsigned)hh < HH) && ((unsigned)w < WW);
        uint32_t off = (tr*34 + tcc)*256 + ((slot ^ (tcc & 7)) << 4);
        uint4 val = make_uint4(0u, 0u, 0u, 0u);
        if (ok) {
            const float4* src = (const float4*)
                (in + ((size_t)((b*HH + hh)*WW + w))*CIN) + slot*2;
            float4 v0 = __ldcs(src);
            float4 v1 = __ldcs(src + 1);
            __half2 p0 = __floats2half2_rn(v0.x, v0.y);
            __half2 p1 = __floats2half2_rn(v0.z, v0.w);
            __half2 p2 = __floats2half2_rn(v1.x, v1.y);
            __half2 p3 = __floats2half2_rn(v1.z, v1.w);
            val.x = *(uint32_t*)&p0; val.y = *(uint32_t*)&p1;
            val.z = *(uint32_t*)&p2; val.w = *(uint32_t*)&p3;
        }
        *(uint4*)(sm + off) = val;
    }
    __syncthreads();

    const int m0 = fr_row;            // local w of the two m fragments
    const int m1 = 16 + fr_row;

    #pragma unroll 2
    for (int c = 0; c < 18; c++) {
        const int tap = c >> 1, cih = c & 1;
        const int dh = tap / 3, dw = tap - dh*3;

        const int tc0 = m0 + dw, tc1 = m1 + dw;
        const uint32_t sw0 = (uint32_t)(tc0 & 7) << 4;
        const uint32_t sw1 = (uint32_t)(tc1 & 7) << 4;
        const uint32_t swhi0 = sw0 & 0x60u, swhi1 = sw1 & 0x60u;
        const uint32_t cb0 = smb + (dh*34 + tc0)*256
                           + ((uint32_t)fr_kb ^ (sw0 & 0x10u)) + cih*128;
        const uint32_t cb1 = smb + (dh*34 + tc1)*256
                           + ((uint32_t)fr_kb ^ (sw1 & 0x10u)) + cih*128;

        const uint4* wfb = g_wF + (((tap*2 + cih)*4 + wid)*16)*32 + lane;
        #pragma unroll
        for (int ks = 0; ks < 4; ks++) {
            uint4 bv[4];
            #pragma unroll
            for (int ng = 0; ng < 4; ng++)
                bv[ng] = wfb[(ng*4 + ks)*32];
            uint32_t aH[2][4];
            ldm4(aH[0], cb0 + ((uint32_t)(ks*32) ^ swhi0));
            ldm4(aH[1], cb1 + ((uint32_t)(ks*32) ^ swhi1));
            #pragma unroll
            for (int ng = 0; ng < 4; ng++) {
                #pragma unroll
                for (int mt = 0; mt < 2; mt++) {
                    mma16816(acc[mt][ng*2],     aH[mt], bv[ng].x, bv[ng].z);
                    mma16816(acc[mt][ng*2 + 1], aH[mt], bv[ng].y, bv[ng].w);
                }
            }
        }
    }
    __syncthreads();

    // ---- epilogue: bias + relu, fp16 store, column sums ----
    float* cs = (float*)(sm + CS_OFF);   // [256]
    const int r  = lane >> 2;
    const int cp = (lane & 3) * 2;

    float csum[8][2];
    #pragma unroll
    for (int nt = 0; nt < 8; nt++) { csum[nt][0] = 0.f; csum[nt][1] = 0.f; }

    #pragma unroll
    for (int mt = 0; mt < 2; mt++) {
        #pragma unroll
        for (int half = 0; half < 2; half++) {
            const int m = mt*16 + r + half*8;          // local w 0..31
            __half* dst = g_x + ((size_t)((b*HH + h)*WW + w0 + m))*CO + wn;
            #pragma unroll
            for (int nt = 0; nt < 8; nt++) {
                float o0 = fmaxf(acc[mt][nt][half*2]     + sbias[wn + nt*8 + cp],     0.f);
                float o1 = fmaxf(acc[mt][nt][half*2 + 1] + sbias[wn + nt*8 + cp + 1], 0.f);
                *(__half2*)(dst + nt*8 + cp) = __floats2half2_rn(o0, o1);
                csum[nt][0] += o0;
                csum[nt][1] += o1;
            }
        }
    }
    #pragma unroll
    for (int nt = 0; nt < 8; nt++) {
        #pragma unroll
        for (int j = 0; j < 2; j++) {
            float v = csum[nt][j];
            v += __shfl_xor_sync(0xffffffffu, v, 4);
            v += __shfl_xor_sync(0xffffffffu, v, 8);
            v += __shfl_xor_sync(0xffffffffu, v, 16);
            if (lane < 4) cs[wn + nt*8 + cp + j] = v;
        }
    }
    __syncthreads();
    float* p0o = g_p0 + ((size_t)b*128 + bx)*256;
    p0o[tid]       = cs[tid];
    p0o[tid + 128] = cs[tid + 128];
}

// ---------------- routing pass over fp16 x ----------------
// grid (64, BN); each warp runs 4 iterations x 2 independent position
// streams (n, n+32) whose shuffle chains interleave for ILP.
__global__ void __launch_bounds__(256)
pass_kernel(const float* __restrict__ vvec, float* __restrict__ part)
{
    const int b    = blockIdx.y;
    const int bx   = blockIdx.x;        // 0..63, 64 n each
    const int wid  = threadIdx.x >> 5;
    const int lane = threadIdx.x & 31;

    float rv[8];
    #pragma unroll
    for (int j = 0; j < 8; j++) rv[j] = vvec[b*256 + lane*8 + j];
    float acc[8];
    #pragma unroll
    for (int j = 0; j < 8; j++) acc[j] = 0.f;

    const __half* xb = g_x + (size_t)b*NPOS*CO;
    int n = bx*64 + wid;
    #pragma unroll
    for (int it = 0; it < 4; it++, n += 8) {
        uint4 rawA = ((const uint4*)(xb + (size_t)n*CO))[lane];
        uint4 rawB = ((const uint4*)(xb + (size_t)(n + 32)*CO))[lane];
        const __half2* pa = (const __half2*)&rawA;
        const __half2* pb = (const __half2*)&rawB;
        float xa[8], xc[8];
        #pragma unroll
        for (int q = 0; q < 4; q++) {
            float2 fa = __half22float2(pa[q]);
            float2 fb = __half22float2(pb[q]);
            xa[2*q] = fa.x; xa[2*q+1] = fa.y;
            xc[2*q] = fb.x; xc[2*q+1] = fb.y;
        }
        float da = 0.f, db = 0.f;
        #pragma unroll
        for (int j = 0; j < 8; j++) { da += xa[j]*rv[j]; db += xc[j]*rv[j]; }
        da += __shfl_xor_sync(0xffffffffu, da, 1);
        db += __shfl_xor_sync(0xffffffffu, db, 1);
        float ma = da, mb = db;
        #pragma unroll
        for (int d = 2; d < 32; d <<= 1) {
            ma = fmaxf(ma, __shfl_xor_sync(0xffffffffu, ma, d));
            mb = fmaxf(mb, __shfl_xor_sync(0xffffffffu, mb, d));
        }
        float ea = __expf(da - ma);
        float eb = __expf(db - mb);
        float sa = ea, sb = eb;
        #pragma unroll
        for (int d = 2; d < 32; d <<= 1) {
            sa += __shfl_xor_sync(0xffffffffu, sa, d);
            sb += __shfl_xor_sync(0xffffffffu, sb, d);
        }
        float ca = ea / sa;
        float cb = eb / sb;
        #pragma unroll
        for (int j = 0; j < 8; j++) acc[j] += ca*xa[j] + cb*xc[j];
    }
    float4* pp = (float4*)(part + ((size_t)(b*512 + bx*8 + wid))*256 + lane*8);
    pp[0] = make_float4(acc[0], acc[1], acc[2], acc[3]);
    pp[1] = make_float4(acc[4], acc[5], acc[6], acc[7]);
}

// ---------------- partial reduce + per-capsule l2 normalize ----------------
__global__ void __launch_bounds__(256)
vnorm_kernel(const float* __restrict__ part, int E,
             const float* __restrict__ addv, float* __restrict__ out)
{
    __shared__ float sv[256];
    __shared__ float tot[32];
    const int b = blockIdx.x, cp2 = blockIdx.y;
    const int t = threadIdx.x;
    const int col = t & 31, slice = t >> 5;
    const int co = cp2*32 + col;
    const int eq = E >> 3;
    const float* p = part + ((size_t)b*E + slice*eq)*256 + co;
    float s = 0.f;
    for (int e = 0; e < eq; e++) s += p[e*256];
    sv[t] = s;
    __syncthreads();
    if (t < 32) {
        float v = sv[t];
        #pragma unroll
        for (int k = 1; k < 8; k++) v += sv[k*32 + t];
        tot[t] = v;
    }
    __syncthreads();
    if (t < 32) {
        const int cb = (t >> 4) << 4;
        float ss = 0.f;
        #pragma unroll
        for (int d = 0; d < 16; d++) { float v = tot[cb + d]; ss += v*v; }
        float r = rsqrtf(fmaxf(ss, 1e-12f));
        float o = tot[t] * r;
        if (addv) o += addv[b*256 + co];
        out[b*256 + co] = o;
    }
}

// ---------------- broadcast v3 ----------------
__global__ void __launch_bounds__(256)
bcast_kernel(float4* __restrict__ out, int total4)
{
    const float4* v = (const float4*)g_v3;
    for (int i = blockIdx.x*blockDim.x + threadIdx.x; i < total4;
         i += gridDim.x*blockDim.x)
        __stcs(out + i, v[((i >> 18) << 6) + (i & 63)]);
}

extern "C" void kernel_launch(void* const* d_in, const int* in_sizes, int n_in,
                              void* d_out, int out_size)
{
    const float* in   = (const float*)d_in[0];
    const float* wk   = (const float*)d_in[1];
    const float* bias = (const float*)d_in[2];

    void *p0, *p2, *p3, *v1, *w, *v3;
    cudaGetSymbolAddress(&p0, g_p0);
    cudaGetSymbolAddress(&p2, g_p2);
    cudaGetSymbolAddress(&p3, g_p3);
    cudaGetSymbolAddress(&v1, g_v1);
    cudaGetSymbolAddress(&w,  g_w);
    cudaGetSymbolAddress(&v3, g_v3);

    cudaFuncSetAttribute(conv_mma_kernel,
                         cudaFuncAttributeMaxDynamicSharedMemorySize, SMEM_CONV);

    split_w_kernel<<<144, 256>>>(wk);

    conv_mma_kernel<<<dim3(2*HH, BN), 128, SMEM_CONV>>>(in, bias);

    vnorm_kernel<<<dim3(BN, 8), 256>>>((const float*)p0, 128, nullptr, (float*)v1);
    pass_kernel<<<dim3(64, BN), 256>>>((const float*)v1, (float*)p2);
    vnorm_kernel<<<dim3(BN, 8), 256>>>((const float*)p2, 512, (const float*)v1, (float*)w);
    pass_kernel<<<dim3(64, BN), 256>>>((const float*)w, (float*)p3);
    vnorm_kernel<<<dim3(BN, 8), 256>>>((const float*)p3, 512, nullptr, (float*)v3);

    bcast_kernel<<<4096, 256>>>((float4*)d_out, out_size >> 2);
}

// round 16
// speedup vs baseline: 1.0315x; 1.0315x over previous
#include <cuda_runtime.h>
#include <cuda_fp16.h>
#include <cstdint>
#include <cstddef>

#define BN   16
#define HH   64
#define WW   64
#define CIN  128
#define CO   256
#define NPOS (HH*WW)

// ---------------- scratch ----------------
__device__ uint4  g_wF[9*2*4*4*4*32];               // fragment-ordered fp16 weights
__device__ __half g_x[(size_t)BN*NPOS*CO];          // relu(conv), fp16, 33.5MB
__device__ float g_p0[BN*128*CO];
__device__ float g_p2[BN*64*CO];
__device__ float g_p3[BN*64*CO];
__device__ float g_v1[BN*CO];
__device__ float g_w [BN*CO];
__device__ float g_v3[BN*CO];

// ---------------- helpers ----------------
__device__ __forceinline__ uint32_t smem_u32(const void* p) {
    uint32_t a;
    asm("{ .reg .u64 t; cvta.to.shared.u64 t, %1; cvt.u32.u64 %0, t; }" : "=r"(a) : "l"(p));
    return a;
}
__device__ __forceinline__ void ldm4(uint32_t* r, uint32_t a) {
    asm volatile("ldmatrix.sync.aligned.m8n8.x4.shared.b16 {%0,%1,%2,%3}, [%4];"
                 : "=r"(r[0]), "=r"(r[1]), "=r"(r[2]), "=r"(r[3]) : "r"(a));
}
__device__ __forceinline__ void mma16816(float* c, const uint32_t* a,
                                         uint32_t b0, uint32_t b1) {
    asm volatile(
        "mma.sync.aligned.m16n8k16.row.col.f32.f16.f16.f32 "
        "{%0,%1,%2,%3}, {%4,%5,%6,%7}, {%8,%9}, {%0,%1,%2,%3};"
        : "+f"(c[0]), "+f"(c[1]), "+f"(c[2]), "+f"(c[3])
        : "r"(a[0]), "r"(a[1]), "r"(a[2]), "r"(a[3]), "r"(b0), "r"(b1));
}

// ---------------- prep: fragment-ordered fp16 weights ----------------
__global__ void __launch_bounds__(256)
split_w_kernel(const float* __restrict__ wk)
{
    int t = blockIdx.x*blockDim.x + threadIdx.x;
    if (t >= 36864) return;
    int lane = t & 31;
    int g = t >> 5;
    int ks = g & 3, ng = (g >> 2) & 3, wnIdx = (g >> 4) & 3;
    int cih = (g >> 6) & 1, tap = g >> 7;
    __half h[8];
    #pragma unroll
    for (int j = 0; j < 8; j++) {
        int m = j >> 1, jj = j & 1;
        int n = wnIdx*64 + ng*16 + (m & 1)*8 + (lane >> 2);
        int k = tap*128 + cih*64 + ks*16 + (m >> 1)*8 + (lane & 3)*2 + jj;
        h[j] = __float2half_rn(wk[k*256 + n]);
    }
    g_wF[t] = *(uint4*)h;
}

// ---------------- tensor-core conv ----------------
// CTA: 32m (half image row) x 256n, 128 threads, 4 warps (1m x 4n),
// warp tile 32m x 64n. 4 CTAs/SM (16 warps/SM, 4/SMSP).
#define HALO_B    26112            // 3*34*256
#define CS_OFF    HALO_B
#define BIAS_OFF  (CS_OFF + 1024)
#define SMEM_CONV (BIAS_OFF + 1024)

__global__ void __launch_bounds__(128, 4)
conv_mma_kernel(const float* __restrict__ in, const float* __restrict__ bias)
{
    extern __shared__ char sm[];
    const uint32_t smb = smem_u32(sm);
    const int tid = threadIdx.x;
    const int bx = blockIdx.x;        // 0..127: half-row index
    const int b  = blockIdx.y;
    const int h  = bx >> 1;
    const int w0 = (bx & 1) * 32;

    float* sbias = (float*)(sm + BIAS_OFF);
    sbias[tid]       = bias[tid];
    sbias[tid + 128] = bias[tid + 128];

    const int wid = tid >> 5, lane = tid & 31;
    const int wn = wid * 64;            // n warp 0..3
    const int lmat = lane >> 3, lrow = lane & 7;
    const int fr_row = (lmat & 1)*8 + lrow;
    const int fr_kb  = (lmat >> 1)*16;      // bit 4

    float acc[2][8][4];
    #pragma unroll
    for (int mt = 0; mt < 2; mt++)
        #pragma unroll
        for (int nt = 0; nt < 8; nt++)
            #pragma unroll
            for (int j = 0; j < 4; j++) acc[mt][nt][j] = 0.f;

    // ---- A halo: 3 rows x 34 cols x 16 slots, fp32 -> fp16, swizzled ----
    for (int i = tid; i < 1632; i += 128) {
        int pix  = i >> 4;
        int slot = i & 15;
        int tr = pix / 34, tcc = pix - tr*34;
        int hh = h + tr - 1, w = w0 + tcc - 1;
        bool ok = ((unsigned)hh < HH) && ((unsigned)w < WW);
        uint32_t off = (tr*34 + tcc)*256 + ((slot ^ (tcc & 7)) << 4);
        uint4 val = make_uint4(0u, 0u, 0u, 0u);
        if (ok) {
            const float4* src = (const float4*)
                (in + ((size_t)((b*HH + hh)*WW + w))*CIN) + slot*2;
            float4 v0 = __ldcs(src);
            float4 v1 = __ldcs(src + 1);
            __half2 p0 = __floats2half2_rn(v0.x, v0.y);
            __half2 p1 = __floats2half2_rn(v0.z, v0.w);
            __half2 p2 = __floats2half2_rn(v1.x, v1.y);
            __half2 p3 = __floats2half2_rn(v1.z, v1.w);
            val.x = *(uint32_t*)&p0; val.y = *(uint32_t*)&p1;
            val.z = *(uint32_t*)&p2; val.w = *(uint32_t*)&p3;
        }
        *(uint4*)(sm + off) = val;
    }
    __syncthreads();

    const int m0 = fr_row;            // local w of the two m fragments
    const int m1 = 16 + fr_row;

    #pragma unroll 2
    for (int c = 0; c < 18; c++) {
        const int tap = c >> 1, cih = c & 1;
        const int dh = tap / 3, dw = tap - dh*3;

        const int tc0 = m0 + dw, tc1 = m1 + dw;
        const uint32_t sw0 = (uint32_t)(tc0 & 7) << 4;
        const uint32_t sw1 = (uint32_t)(tc1 & 7) << 4;
        const uint32_t swhi0 = sw0 & 0x60u, swhi1 = sw1 & 0x60u;
        const uint32_t cb0 = smb + (dh*34 + tc0)*256
                           + ((uint32_t)fr_kb ^ (sw0 & 0x10u)) + cih*128;
        const uint32_t cb1 = smb + (dh*34 + tc1)*256
                           + ((uint32_t)fr_kb ^ (sw1 & 0x10u)) + cih*128;

        const uint4* wfb = g_wF + (((tap*2 + cih)*4 + wid)*16)*32 + lane;
        #pragma unroll
        for (int ks = 0; ks < 4; ks++) {
            uint4 bv[4];
            #pragma unroll
            for (int ng = 0; ng < 4; ng++)
                bv[ng] = wfb[(ng*4 + ks)*32];
            uint32_t aH[2][4];
            ldm4(aH[0], cb0 + ((uint32_t)(ks*32) ^ swhi0));
            ldm4(aH[1], cb1 + ((uint32_t)(ks*32) ^ swhi1));
            #pragma unroll
            for (int ng = 0; ng < 4; ng++) {
                #pragma unroll
                for (int mt = 0; mt < 2; mt++) {
                    mma16816(acc[mt][ng*2],     aH[mt], bv[ng].x, bv[ng].z);
                    mma16816(acc[mt][ng*2 + 1], aH[mt], bv[ng].y, bv[ng].w);
                }
            }
        }
    }
    __syncthreads();

    // ---- epilogue: bias + relu, fp16 store, column sums ----
    float* cs = (float*)(sm + CS_OFF);   // [256]
    const int r  = lane >> 2;
    const int cp = (lane & 3) * 2;

    float csum[8][2];
    #pragma unroll
    for (int nt = 0; nt < 8; nt++) { csum[nt][0] = 0.f; csum[nt][1] = 0.f; }

    #pragma unroll
    for (int mt = 0; mt < 2; mt++) {
        #pragma unroll
        for (int half = 0; half < 2; half++) {
            const int m = mt*16 + r + half*8;          // local w 0..31
            __half* dst = g_x + ((size_t)((b*HH + h)*WW + w0 + m))*CO + wn;
            #pragma unroll
            for (int nt = 0; nt < 8; nt++) {
                float o0 = fmaxf(acc[mt][nt][half*2]     + sbias[wn + nt*8 + cp],     0.f);
                float o1 = fmaxf(acc[mt][nt][half*2 + 1] + sbias[wn + nt*8 + cp + 1], 0.f);
                *(__half2*)(dst + nt*8 + cp) = __floats2half2_rn(o0, o1);
                csum[nt][0] += o0;
                csum[nt][1] += o1;
            }
        }
    }
    #pragma unroll
    for (int nt = 0; nt < 8; nt++) {
        #pragma unroll
        for (int j = 0; j < 2; j++) {
            float v = csum[nt][j];
            v += __shfl_xor_sync(0xffffffffu, v, 4);
            v += __shfl_xor_sync(0xffffffffu, v, 8);
            v += __shfl_xor_sync(0xffffffffu, v, 16);
            if (lane < 4) cs[wn + nt*8 + cp + j] = v;
        }
    }
    __syncthreads();
    float* p0o = g_p0 + ((size_t)b*128 + bx)*256;
    p0o[tid]       = cs[tid];
    p0o[tid + 128] = cs[tid + 128];
}

// ---------------- routing pass over fp16 x ----------------
// grid (64, BN); each warp: 4 iters x 2 independent position streams.
// Shift-free softmax (bounded dots) -> 5-shuffle chain. Block-level
// partial reduce: one 256-vec per CTA.
__global__ void __launch_bounds__(256)
pass_kernel(const float* __restrict__ vvec, float* __restrict__ part)
{
    __shared__ float sred[8*256];
    const int b    = blockIdx.y;
    const int bx   = blockIdx.x;        // 0..63, 64 n each
    const int wid  = threadIdx.x >> 5;
    const int lane = threadIdx.x & 31;

    float rv[8];
    #pragma unroll
    for (int j = 0; j < 8; j++) rv[j] = vvec[b*256 + lane*8 + j];
    float acc[8];
    #pragma unroll
    for (int j = 0; j < 8; j++) acc[j] = 0.f;

    const __half* xb = g_x + (size_t)b*NPOS*CO;
    int n = bx*64 + wid;
    #pragma unroll
    for (int it = 0; it < 4; it++, n += 8) {
        uint4 rawA = ((const uint4*)(xb + (size_t)n*CO))[lane];
        uint4 rawB = ((const uint4*)(xb + (size_t)(n + 32)*CO))[lane];
        const __half2* pa = (const __half2*)&rawA;
        const __half2* pb = (const __half2*)&rawB;
        float xa[8], xc[8];
        #pragma unroll
        for (int q = 0; q < 4; q++) {
            float2 fa = __half22float2(pa[q]);
            float2 fb = __half22float2(pb[q]);
            xa[2*q] = fa.x; xa[2*q+1] = fa.y;
            xc[2*q] = fb.x; xc[2*q+1] = fb.y;
        }
        float da = 0.f, db = 0.f;
        #pragma unroll
        for (int j = 0; j < 8; j++) { da += xa[j]*rv[j]; db += xc[j]*rv[j]; }
        da += __shfl_xor_sync(0xffffffffu, da, 1);   // full capsule dot
        db += __shfl_xor_sync(0xffffffffu, db, 1);
        // shift-free softmax (dots bounded ~O(10), exp safe in fp32)
        float ea = __expf(da);
        float eb = __expf(db);
        float sa = ea, sb = eb;
        #pragma unroll
        for (int d = 2; d < 32; d <<= 1) {
            sa += __shfl_xor_sync(0xffffffffu, sa, d);
            sb += __shfl_xor_sync(0xffffffffu, sb, d);
        }
        float ca = ea / sa;
        float cb = eb / sb;
        #pragma unroll
        for (int j = 0; j < 8; j++) acc[j] += ca*xa[j] + cb*xc[j];
    }
    // block-level reduce: 8 warps -> 1 vector of 256
    #pragma unroll
    for (int j = 0; j < 8; j++) sred[wid*256 + lane*8 + j] = acc[j];
    __syncthreads();
    const int t = threadIdx.x;
    float s = sred[t];
    #pragma unroll
    for (int k = 1; k < 8; k++) s += sred[k*256 + t];
    part[((size_t)(b*64 + bx))*256 + t] = s;
}

// ---------------- partial reduce + per-capsule l2 normalize ----------------
// grid (16 b, 8 capsule-pairs); block = 32 co x 8 E-slices.
__global__ void __launch_bounds__(256)
vnorm_kernel(const float* __restrict__ part, int E,
             const float* __restrict__ addv, float* __restrict__ out)
{
    __shared__ float sv[256];
    __shared__ float tot[32];
    const int b = blockIdx.x, cp2 = blockIdx.y;
    const int t = threadIdx.x;
    const int col = t & 31, slice = t >> 5;
    const int co = cp2*32 + col;
    const int eq = E >> 3;
    const float* p = part + ((size_t)b*E + slice*eq)*256 + co;
    float s = 0.f;
    for (int e = 0; e < eq; e++) s += p[e*256];
    sv[t] = s;
    __syncthreads();
    if (t < 32) {
        float v = sv[t];
        #pragma unroll
        for (int k = 1; k < 8; k++) v += sv[k*32 + t];
        tot[t] = v;
    }
    __syncthreads();
    if (t < 32) {
        const int cb = (t >> 4) << 4;
        float ss = 0.f;
        #pragma unroll
        for (int d = 0; d < 16; d++) { float v = tot[cb + d]; ss += v*v; }
        float r = rsqrtf(fmaxf(ss, 1e-12f));
        float o = tot[t] * r;
        if (addv) o += addv[b*256 + co];
        out[b*256 + co] = o;
    }
}

// ---------------- broadcast v3 ----------------
__global__ void __launch_bounds__(256)
bcast_kernel(float4* __restrict__ out, int total4)
{
    const float4* v = (const float4*)g_v3;
    for (int i = blockIdx.x*blockDim.x + threadIdx.x; i < total4;
         i += gridDim.x*blockDim.x)
        __stcs(out + i, v[((i >> 18) << 6) + (i & 63)]);
}

extern "C" void kernel_launch(void* const* d_in, const int* in_sizes, int n_in,
                              void* d_out, int out_size)
{
    const float* in   = (const float*)d_in[0];
    const float* wk   = (const float*)d_in[1];
    const float* bias = (const float*)d_in[2];

    void *p0, *p2, *p3, *v1, *w, *v3;
    cudaGetSymbolAddress(&p0, g_p0);
    cudaGetSymbolAddress(&p2, g_p2);
    cudaGetSymbolAddress(&p3, g_p3);
    cudaGetSymbolAddress(&v1, g_v1);
    cudaGetSymbolAddress(&w,  g_w);
    cudaGetSymbolAddress(&v3, g_v3);

    cudaFuncSetAttribute(conv_mma_kernel,
                         cudaFuncAttributeMaxDynamicSharedMemorySize, SMEM_CONV);

    split_w_kernel<<<144, 256>>>(wk);

    conv_mma_kernel<<<dim3(2*HH, BN), 128, SMEM_CONV>>>(in, bias);

    vnorm_kernel<<<dim3(BN, 8), 256>>>((const float*)p0, 128, nullptr, (float*)v1);
    pass_kernel<<<dim3(64, BN), 256>>>((const float*)v1, (float*)p2);
    vnorm_kernel<<<dim3(BN, 8), 256>>>((const float*)p2, 64, (const float*)v1, (float*)w);
    pass_kernel<<<dim3(64, BN), 256>>>((const float*)w, (float*)p3);
    vnorm_kernel<<<dim3(BN, 8), 256>>>((const float*)p3, 64, nullptr, (float*)v3);

    bcast_kernel<<<4096, 256>>>((float4*)d_out, out_size >> 2);
}